// round 14
// baseline (speedup 1.0000x reference)
#include <cuda_runtime.h>
#include <cuda_fp16.h>
#include <cstdint>

#define BSZ  2048
#define TLEN 12
#define HIDD 1024
#define NCLS 51
#define MROWS (TLEN * BSZ)   // 24576

// GEMM tiling: 128x128 CTA tile, 256 threads, 2 CTAs/SM
#define BM 128
#define BN 128
#define NSTAGE 3
#define A_STAGE_BYTES 16384         // 128 rows x 128B
#define B_STAGE_BYTES 16384         // 128 rows x 128B
#define STAGE_BYTES (A_STAGE_BYTES + B_STAGE_BYTES)   // 32KB
#define SMEM_TOTAL (NSTAGE * STAGE_BYTES)             // 96KB

// ---------------- scratch (device globals; no allocation allowed) -----------
__device__ __align__(16) __half g_U  [(size_t)MROWS * 4096];  // [u0|u1|u2|resid] fp16
__device__ __align__(16) float  g_g  [(size_t)BSZ   * HIDD];
__device__ __align__(16) __half g_ah [(size_t)MROWS * HIDD];  // activations fp16
__device__ __align__(16) __half g_wh0[(size_t)4096 * 512];    // W0t fp16 [N,K]
__device__ __align__(16) __half g_wh1[(size_t)3072 * 1024];   // W1t fp16 [N,K]
__device__ __align__(16) __half g_wh2[(size_t)3072 * 1024];   // W2t fp16 [N,K]

// ---------------- helpers ----------------------------------------------------
__device__ __forceinline__ uint32_t smem_u32(const void* p) {
    uint32_t a;
    asm("{ .reg .u64 t; cvta.to.shared.u64 t, %1; cvt.u32.u64 %0, t; }" : "=r"(a) : "l"(p));
    return a;
}
#define SWZ(o) ((uint32_t)(o) ^ ((((uint32_t)(o)) >> 3) & 0x70))

__device__ __forceinline__ void cp16(uint32_t s, const void* g) {
    asm volatile("cp.async.cg.shared.global [%0], [%1], 16;" :: "r"(s), "l"(g));
}
#define CP_COMMIT() asm volatile("cp.async.commit_group;" ::: "memory")
#define CP_WAIT1()  asm volatile("cp.async.wait_group 1;" ::: "memory")

#define LDSM4(r, addr) \
    asm volatile("ldmatrix.sync.aligned.m8n8.x4.shared.b16 {%0,%1,%2,%3}, [%4];" \
        : "=r"((r)[0]), "=r"((r)[1]), "=r"((r)[2]), "=r"((r)[3]) : "r"(addr))

#define MMA(d, a, b) \
    asm volatile("mma.sync.aligned.m16n8k16.row.col.f32.f16.f16.f32 " \
        "{%0,%1,%2,%3}, {%4,%5,%6,%7}, {%8,%9}, {%0,%1,%2,%3};" \
        : "+f"((d)[0]), "+f"((d)[1]), "+f"((d)[2]), "+f"((d)[3]) \
        : "r"((a)[0]), "r"((a)[1]), "r"((a)[2]), "r"((a)[3]), "r"((b)[0]), "r"((b)[1]))

// fast sigmoid / tanh (MUFU-based, non-arch-gated PTX)
__device__ __forceinline__ float sigf(float z) {
    float e = __expf(-z);
    float r;
    asm("rcp.approx.f32 %0, %1;" : "=f"(r) : "f"(1.f + e));
    return r;
}
__device__ __forceinline__ float tanhfast(float z) {
    float r;
    asm("tanh.approx.f32 %0, %1;" : "=f"(r) : "f"(z));
    return r;
}

// ---------------- mma.sync fp16 GEMM (+piggy-backed weight transpose) --------
// Blocks with blockIdx.x < nxg: U[M,N] = A[M,K] @ B[N,K]^T (fp16 out, smem-
// staged epilogue). Blocks with blockIdx.x >= nxg: transpose+convert the NEXT
// layer's weights Wn [Kn,Nn] fp32 -> Whn [Nn,Kn] fp16 (overlaps with GEMM).
__global__ __launch_bounds__(256, 2)
void gemm_tc(const __half* __restrict__ A, const __half* __restrict__ B,
             __half* __restrict__ U, int N, int K, int nxg,
             const float* __restrict__ Wn, __half* __restrict__ Whn,
             int Kn, int Nn)
{
    extern __shared__ char smem[];

    if ((int)blockIdx.x >= nxg) {
        // ---- embedded weight transpose (32x32 tile per block) ----
        int extra = (blockIdx.x - nxg) * gridDim.y + blockIdx.y;
        int nTiles = (Kn >> 5) * (Nn >> 5);
        if (extra >= nTiles) return;
        int ntPerRow = Nn >> 5;
        int k0 = (extra / ntPerRow) * 32;
        int n0 = (extra % ntPerRow) * 32;
        float* t = (float*)smem;                 // 32x33 padded tile
        const int tx = threadIdx.x & 31, ty = threadIdx.x >> 5;  // 32x8
#pragma unroll
        for (int j = 0; j < 32; j += 8)
            t[(ty + j) * 33 + tx] = Wn[(size_t)(k0 + ty + j) * Nn + n0 + tx];
        __syncthreads();
#pragma unroll
        for (int j = 0; j < 32; j += 8)
            Whn[(size_t)(n0 + ty + j) * Kn + k0 + tx] =
                __float2half_rn(t[tx * 33 + ty + j]);
        return;
    }

    const int tid = threadIdx.x, lane = tid & 31, wid = tid >> 5;
    const uint32_t sb = smem_u32(smem);
    const size_t bm = (size_t)blockIdx.y * BM;
    const size_t bn = (size_t)blockIdx.x * BN;
    const int nch = K >> 6;

    // 8 warps: 2 (M) x 4 (N); warp tile 64x32
    const int m0w = (wid & 1) * 64;
    const int n0w = (wid >> 1) * 32;
    const int rA = lane & 15;
    const int cA = (lane & 16) ? 16 : 0;
    const int rB = (lane & 7) | ((lane & 16) >> 1);
    const int cB = (lane & 8) ? 16 : 0;

    float acc[4][4][4];
#pragma unroll
    for (int i = 0; i < 4; i++)
#pragma unroll
        for (int j = 0; j < 4; j++)
#pragma unroll
            for (int q = 0; q < 4; q++) acc[i][j][q] = 0.f;

    auto loadStage = [&](int c, int s) {
        if (c >= nch) return;
        const int k0 = c << 6;
        const uint32_t sa = sb + s * STAGE_BYTES;
        const uint32_t sB = sa + A_STAGE_BYTES;
#pragma unroll
        for (int ii = 0; ii < 4; ii++) {
            int i = tid + ii * 256;
            int row = i >> 3, c16 = i & 7;
            cp16(sa + SWZ(row * 128 + c16 * 16),
                 A + (bm + row) * (size_t)K + k0 + c16 * 8);
        }
#pragma unroll
        for (int ii = 0; ii < 4; ii++) {
            int i = tid + ii * 256;
            int row = i >> 3, c16 = i & 7;
            cp16(sB + SWZ(row * 128 + c16 * 16),
                 B + (bn + row) * (size_t)K + k0 + c16 * 8);
        }
    };

    loadStage(0, 0); CP_COMMIT();
    loadStage(1, 1); CP_COMMIT();

    int stage = 0;
    for (int c = 0; c < nch; c++) {
        CP_WAIT1();                 // chunk c resident (pending <= 1)
        __syncthreads();
        {
            int ws = stage + 2;     // distance-2 prefetch (distinct from c, c+1)
            if (ws >= NSTAGE) ws -= NSTAGE;
            loadStage(c + 2, ws);
        }
        CP_COMMIT();

        const uint32_t sa = sb + stage * STAGE_BYTES;
        const uint32_t sB = sa + A_STAGE_BYTES;
        stage = (stage + 1 == NSTAGE) ? 0 : stage + 1;

#pragma unroll
        for (int ks = 0; ks < 4; ks++) {
            uint32_t a[4][4], b[4][2];
#pragma unroll
            for (int np = 0; np < 2; np++) {
                uint32_t r4[4];
                LDSM4(r4, sB + SWZ((n0w + np * 16 + rB) * 128 + ks * 32 + cB));
                b[np * 2][0] = r4[0]; b[np * 2][1] = r4[1];
                b[np * 2 + 1][0] = r4[2]; b[np * 2 + 1][1] = r4[3];
            }
#pragma unroll
            for (int mt = 0; mt < 4; mt++)
                LDSM4(a[mt], sa + SWZ((m0w + mt * 16 + rA) * 128 + ks * 32 + cA));
#pragma unroll
            for (int mt = 0; mt < 4; mt++)
#pragma unroll
                for (int nt = 0; nt < 4; nt++) MMA(acc[mt][nt], a[mt], b[nt]);
        }
    }

    // ---- epilogue: stage fp16 tile in smem (256B rows, SWZ), then coalesce --
    __syncthreads();   // mainloop smem dead; no real cp.async pending
    const int g = lane >> 2, t = lane & 3;
#pragma unroll
    for (int mt = 0; mt < 4; mt++) {
#pragma unroll
        for (int nt = 0; nt < 4; nt++) {
            int row = m0w + mt * 16 + g;
            int colb = (n0w + nt * 8 + t * 2) * 2;
            *(__half2*)(smem + SWZ(row * 256 + colb)) =
                __floats2half2_rn(acc[mt][nt][0], acc[mt][nt][1]);
            *(__half2*)(smem + SWZ((row + 8) * 256 + colb)) =
                __floats2half2_rn(acc[mt][nt][2], acc[mt][nt][3]);
        }
    }
    __syncthreads();
    // copy out: 128 rows x 256B; 16 lanes cover one full row (coalesced 16B each)
#pragma unroll
    for (int k = 0; k < 8; k++) {
        int chunk = tid + k * 256;          // 2048 x 16B chunks
        int row = chunk >> 4, c16 = chunk & 15;
        uint4 v = *(uint4*)(smem + SWZ(row * 256 + c16 * 16));
        *(uint4*)(U + (bm + row) * (size_t)N + bn + c16 * 8) = v;
    }
}

// ---------------- x -> fp16 with (B,T)->(T,B) remap --------------------------
__global__ __launch_bounds__(256)
void conv_x(const float* __restrict__ x, __half* __restrict__ ah)
{
    size_t i = (size_t)blockIdx.x * blockDim.x + threadIdx.x;  // over T*B*512
    int d = i & 511;
    size_t r = i >> 9;
    int b = (int)(r & (BSZ - 1));
    int t = (int)(r >> 11);
    ah[i] = __float2half_rn(x[((size_t)b * TLEN + t) * 512 + d]);
}

// ---------------- W[K,N] -> Wt fp16 [N,K] (standalone, for W0) ---------------
__global__ __launch_bounds__(256)
void conv_wt(const float* __restrict__ W, __half* __restrict__ Wh, int K, int N)
{
    __shared__ float t[32][33];
    const int n0 = blockIdx.x * 32, k0 = blockIdx.y * 32;
    const int tx = threadIdx.x & 31, ty = threadIdx.x >> 5;  // 32x8
#pragma unroll
    for (int j = 0; j < 32; j += 8)
        t[ty + j][tx] = W[(size_t)(k0 + ty + j) * N + n0 + tx];
    __syncthreads();
#pragma unroll
    for (int j = 0; j < 32; j += 8)
        Wh[(size_t)(n0 + ty + j) * K + k0 + tx] = __float2half_rn(t[tx][ty + j]);
}

// ---------------- SRU recurrence (2-wide, software-pipelined, all-fp16 U) ----
// U row layout: u0 at +0, u1 at +1024, u2 at +2048, resid at +3072 (layer 0).
// w = U row stride (4096 layer 0, 3072 otherwise). resid otherwise from hbuf
// (fp16, in-place overwrite; same thread owns each element).
// g_out!=nullptr (final layer): emit time-sum instead of h.
__global__ __launch_bounds__(256, 6)
void sru_k(const __half* __restrict__ U, int w, int resid_in_u,
           const float* __restrict__ vc, const float* __restrict__ bvec,
           __half* __restrict__ hbuf, float* __restrict__ g_out)
{
    const float SCALE_X = 1.7320508075688772f;
    int idx = blockIdx.x * blockDim.x + threadIdx.x;  // over BSZ*512
    int d = (idx & 511) * 2;
    int b = idx >> 9;
    float2 vf = *(const float2*)(vc + d);
    float2 vr = *(const float2*)(vc + HIDD + d);
    float2 bf = *(const float2*)(bvec + d);
    float2 br = *(const float2*)(bvec + HIDD + d);
    float cx = 0.f, cy = 0.f, gx = 0.f, gy = 0.f;

    // prefetch t=0
    const __half* Up0 = U + (size_t)b * w + d;
    __half2 u0h = *(const __half2*)(Up0);
    __half2 u1h = *(const __half2*)(Up0 + 1024);
    __half2 u2h = *(const __half2*)(Up0 + 2048);
    __half2 xrh;
    if (resid_in_u) xrh = *(const __half2*)(Up0 + 3072);
    else            xrh = *(const __half2*)(hbuf + (size_t)b * HIDD + d);

#pragma unroll
    for (int t = 0; t < TLEN; t++) {
        __half2 u0n = u0h, u1n = u1h, u2n = u2h, xrn = xrh;
        if (t + 1 < TLEN) {
            const __half* Upn = U + ((size_t)(t + 1) * BSZ + b) * w + d;
            u0n = *(const __half2*)(Upn);
            u1n = *(const __half2*)(Upn + 1024);
            u2n = *(const __half2*)(Upn + 2048);
            if (resid_in_u) xrn = *(const __half2*)(Upn + 3072);
            else xrn = *(const __half2*)(hbuf + ((size_t)(t + 1) * BSZ + b) * HIDD + d);
        }
        float2 u0 = __half22float2(u0h);
        float2 u1 = __half22float2(u1h);
        float2 u2 = __half22float2(u2h);
        float2 xr = __half22float2(xrh);
        float fx = sigf(u1.x + vf.x * cx + bf.x);
        float fy = sigf(u1.y + vf.y * cy + bf.y);
        cx = fx * cx + (1.f - fx) * u0.x;
        cy = fy * cy + (1.f - fy) * u0.y;
        float rx = sigf(u2.x + vr.x * cx + br.x);
        float ry = sigf(u2.y + vr.y * cy + br.y);
        float hx = rx * tanhfast(cx) + (1.f - rx) * xr.x * SCALE_X;
        float hy = ry * tanhfast(cy) + (1.f - ry) * xr.y * SCALE_X;
        if (g_out) { gx += hx; gy += hy; }
        else *(__half2*)(hbuf + ((size_t)t * BSZ + b) * HIDD + d) = __floats2half2_rn(hx, hy);
        u0h = u0n; u1h = u1n; u2h = u2n; xrh = xrn;
    }
    if (g_out) *(float2*)(g_out + (size_t)b * HIDD + d) = make_float2(gx, gy);
}

// ---------------- FC head: 8 batch rows per block ----------------------------
__global__ __launch_bounds__(256)
void fc_k(const float* __restrict__ g, const float* __restrict__ w,
          const float* __restrict__ bias, float* __restrict__ out)
{
    __shared__ float gs[8][HIDD];
    const int b0 = blockIdx.x * 8;
    for (int i = threadIdx.x; i < 8 * HIDD; i += 256)
        gs[i >> 10][i & 1023] = g[(size_t)(b0 + (i >> 10)) * HIDD + (i & 1023)];
    __syncthreads();
    const int c = threadIdx.x & 63, bq = threadIdx.x >> 6;   // 4 groups x 2 rows
    if (c < NCLS) {
        float bb = bias[c];
#pragma unroll
        for (int j = 0; j < 2; j++) {
            int bl = bq * 2 + j;
            float s = 0.f;
#pragma unroll 8
            for (int hh = 0; hh < HIDD; hh++) s += gs[bl][hh] * w[hh * NCLS + c];
            out[(size_t)(b0 + bl) * NCLS + c] = s * (1.f / TLEN) + bb;
        }
    }
}

// ---------------- launch -----------------------------------------------------
extern "C" void kernel_launch(void* const* d_in, const int* in_sizes, int n_in,
                              void* d_out, int out_size)
{
    const float* x    = (const float*)d_in[0];
    const float* W0   = (const float*)d_in[1];
    const float* W1   = (const float*)d_in[2];
    const float* W2   = (const float*)d_in[3];
    const float* vc0  = (const float*)d_in[4];
    const float* vc1  = (const float*)d_in[5];
    const float* vc2  = (const float*)d_in[6];
    const float* b0   = (const float*)d_in[7];
    const float* b1   = (const float*)d_in[8];
    const float* b2   = (const float*)d_in[9];
    const float* fcw  = (const float*)d_in[10];
    const float* fcb  = (const float*)d_in[11];
    float* out = (float*)d_out;

    float *gg;
    __half *U, *ah, *wh0, *wh1, *wh2;
    cudaGetSymbolAddress((void**)&U,   g_U);
    cudaGetSymbolAddress((void**)&gg,  g_g);
    cudaGetSymbolAddress((void**)&ah,  g_ah);
    cudaGetSymbolAddress((void**)&wh0, g_wh0);
    cudaGetSymbolAddress((void**)&wh1, g_wh1);
    cudaGetSymbolAddress((void**)&wh2, g_wh2);

    cudaFuncSetAttribute(gemm_tc, cudaFuncAttributeMaxDynamicSharedMemorySize, SMEM_TOTAL);

    const int sruBlocks = (BSZ * 512) / 256;

    // prep: x conversion + W0 transpose (on critical path)
    conv_x<<<(TLEN * BSZ * 512) / 256, 256>>>(x, ah);
    conv_wt<<<dim3(4096 / 32, 512 / 32), 256>>>(W0, wh0, 512, 4096);

    // Layer 0 GEMM (grid.x 32 gemm cols + 16 extra cols = 3072 W1-transpose blocks)
    gemm_tc<<<dim3(32 + 16, MROWS / BM), 256, SMEM_TOTAL>>>(
        ah, wh0, U, 4096, 512, 32, W1, wh1, 1024, 3072);
    sru_k<<<sruBlocks, 256>>>(U, 4096, 1, vc0, b0, ah, nullptr);

    // Layer 1 GEMM (24 gemm cols + 16 extra = W2 transpose)
    gemm_tc<<<dim3(24 + 16, MROWS / BM), 256, SMEM_TOTAL>>>(
        ah, wh1, U, 3072, 1024, 24, W2, wh2, 1024, 3072);
    sru_k<<<sruBlocks, 256>>>(U, 3072, 0, vc1, b1, ah, nullptr);

    // Layer 2 GEMM (no extra blocks); final SRU emits time-sum g
    gemm_tc<<<dim3(24, MROWS / BM), 256, SMEM_TOTAL>>>(
        ah, wh2, U, 3072, 1024, 24, nullptr, nullptr, 0, 0);
    sru_k<<<sruBlocks, 256>>>(U, 3072, 0, vc2, b2, ah, gg);

    // Head
    fc_k<<<BSZ / 8, 256>>>(gg, fcw, fcb, out);
}

// round 15
// speedup vs baseline: 1.0023x; 1.0023x over previous
#include <cuda_runtime.h>
#include <cuda_fp16.h>
#include <cstdint>

#define BSZ  2048
#define TLEN 12
#define HIDD 1024
#define NCLS 51
#define MROWS (TLEN * BSZ)   // 24576

// GEMM tiling: 128x128 CTA tile, 256 threads, 2 CTAs/SM
#define BM 128
#define BN 128
#define NSTAGE 3
#define A_STAGE_BYTES 16384         // 128 rows x 128B
#define B_STAGE_BYTES 16384         // 128 rows x 128B
#define STAGE_BYTES (A_STAGE_BYTES + B_STAGE_BYTES)   // 32KB
#define SMEM_TOTAL (NSTAGE * STAGE_BYTES)             // 96KB

// ---------------- scratch (device globals; no allocation allowed) -----------
__device__ __align__(16) __half g_U  [(size_t)MROWS * 4096];  // [u0|u1|u2|resid] fp16
__device__ __align__(16) float  g_g  [(size_t)BSZ   * HIDD];
__device__ __align__(16) __half g_ah [(size_t)MROWS * HIDD];  // activations fp16
__device__ __align__(16) __half g_wh0[(size_t)4096 * 512];    // W0t fp16 [N,K]
__device__ __align__(16) __half g_wh1[(size_t)3072 * 1024];   // W1t fp16 [N,K]
__device__ __align__(16) __half g_wh2[(size_t)3072 * 1024];   // W2t fp16 [N,K]

// ---------------- helpers ----------------------------------------------------
__device__ __forceinline__ uint32_t smem_u32(const void* p) {
    uint32_t a;
    asm("{ .reg .u64 t; cvta.to.shared.u64 t, %1; cvt.u32.u64 %0, t; }" : "=r"(a) : "l"(p));
    return a;
}
#define SWZ(o) ((uint32_t)(o) ^ ((((uint32_t)(o)) >> 3) & 0x70))

__device__ __forceinline__ void cp16(uint32_t s, const void* g) {
    asm volatile("cp.async.cg.shared.global [%0], [%1], 16;" :: "r"(s), "l"(g));
}
#define CP_COMMIT() asm volatile("cp.async.commit_group;" ::: "memory")
#define CP_WAIT1()  asm volatile("cp.async.wait_group 1;" ::: "memory")

#define LDSM4(r, addr) \
    asm volatile("ldmatrix.sync.aligned.m8n8.x4.shared.b16 {%0,%1,%2,%3}, [%4];" \
        : "=r"((r)[0]), "=r"((r)[1]), "=r"((r)[2]), "=r"((r)[3]) : "r"(addr))

#define MMA(d, a, b) \
    asm volatile("mma.sync.aligned.m16n8k16.row.col.f32.f16.f16.f32 " \
        "{%0,%1,%2,%3}, {%4,%5,%6,%7}, {%8,%9}, {%0,%1,%2,%3};" \
        : "+f"((d)[0]), "+f"((d)[1]), "+f"((d)[2]), "+f"((d)[3]) \
        : "r"((a)[0]), "r"((a)[1]), "r"((a)[2]), "r"((a)[3]), "r"((b)[0]), "r"((b)[1]))

// fast sigmoid / tanh (MUFU-based, non-arch-gated PTX)
__device__ __forceinline__ float sigf(float z) {
    float e = __expf(-z);
    float r;
    asm("rcp.approx.f32 %0, %1;" : "=f"(r) : "f"(1.f + e));
    return r;
}
__device__ __forceinline__ float tanhfast(float z) {
    float r;
    asm("tanh.approx.f32 %0, %1;" : "=f"(r) : "f"(z));
    return r;
}

// ---------------- mma.sync fp16 GEMM (+piggy-backed weight transpose) --------
// Blocks with blockIdx.x < nxg: U[M,N] = A[M,K] @ B[N,K]^T (fp16 out, smem-
// staged epilogue). Blocks with blockIdx.x >= nxg: transpose+convert the NEXT
// layer's weights Wn [Kn,Nn] fp32 -> Whn [Nn,Kn] fp16 (overlaps with GEMM).
__global__ __launch_bounds__(256, 2)
void gemm_tc(const __half* __restrict__ A, const __half* __restrict__ B,
             __half* __restrict__ U, int N, int K, int nxg,
             const float* __restrict__ Wn, __half* __restrict__ Whn,
             int Kn, int Nn)
{
    extern __shared__ char smem[];

    if ((int)blockIdx.x >= nxg) {
        // ---- embedded weight transpose (32x32 tile per block) ----
        int extra = (blockIdx.x - nxg) * gridDim.y + blockIdx.y;
        int nTiles = (Kn >> 5) * (Nn >> 5);
        if (extra >= nTiles) return;
        int ntPerRow = Nn >> 5;
        int k0 = (extra / ntPerRow) * 32;
        int n0 = (extra % ntPerRow) * 32;
        float* t = (float*)smem;                 // 32x33 padded tile
        const int tx = threadIdx.x & 31, ty = threadIdx.x >> 5;  // 32x8
#pragma unroll
        for (int j = 0; j < 32; j += 8)
            t[(ty + j) * 33 + tx] = Wn[(size_t)(k0 + ty + j) * Nn + n0 + tx];
        __syncthreads();
#pragma unroll
        for (int j = 0; j < 32; j += 8)
            Whn[(size_t)(n0 + ty + j) * Kn + k0 + tx] =
                __float2half_rn(t[tx * 33 + ty + j]);
        return;
    }

    const int tid = threadIdx.x, lane = tid & 31, wid = tid >> 5;
    const uint32_t sb = smem_u32(smem);
    const size_t bm = (size_t)blockIdx.y * BM;
    const size_t bn = (size_t)blockIdx.x * BN;
    const int nch = K >> 6;

    // 8 warps: 2 (M) x 4 (N); warp tile 64x32
    const int m0w = (wid & 1) * 64;
    const int n0w = (wid >> 1) * 32;
    const int rA = lane & 15;
    const int cA = (lane & 16) ? 16 : 0;
    const int rB = (lane & 7) | ((lane & 16) >> 1);
    const int cB = (lane & 8) ? 16 : 0;

    float acc[4][4][4];
#pragma unroll
    for (int i = 0; i < 4; i++)
#pragma unroll
        for (int j = 0; j < 4; j++)
#pragma unroll
            for (int q = 0; q < 4; q++) acc[i][j][q] = 0.f;

    auto loadStage = [&](int c, int s) {
        if (c >= nch) return;
        const int k0 = c << 6;
        const uint32_t sa = sb + s * STAGE_BYTES;
        const uint32_t sB = sa + A_STAGE_BYTES;
#pragma unroll
        for (int ii = 0; ii < 4; ii++) {
            int i = tid + ii * 256;
            int row = i >> 3, c16 = i & 7;
            cp16(sa + SWZ(row * 128 + c16 * 16),
                 A + (bm + row) * (size_t)K + k0 + c16 * 8);
        }
#pragma unroll
        for (int ii = 0; ii < 4; ii++) {
            int i = tid + ii * 256;
            int row = i >> 3, c16 = i & 7;
            cp16(sB + SWZ(row * 128 + c16 * 16),
                 B + (bn + row) * (size_t)K + k0 + c16 * 8);
        }
    };

    loadStage(0, 0); CP_COMMIT();
    loadStage(1, 1); CP_COMMIT();

    int stage = 0;
    for (int c = 0; c < nch; c++) {
        CP_WAIT1();                 // chunk c resident (pending <= 1)
        __syncthreads();
        {
            int ws = stage + 2;     // distance-2 prefetch (distinct from c, c+1)
            if (ws >= NSTAGE) ws -= NSTAGE;
            loadStage(c + 2, ws);
        }
        CP_COMMIT();

        const uint32_t sa = sb + stage * STAGE_BYTES;
        const uint32_t sB = sa + A_STAGE_BYTES;
        stage = (stage + 1 == NSTAGE) ? 0 : stage + 1;

#pragma unroll
        for (int ks = 0; ks < 4; ks++) {
            uint32_t a[4][4], b[4][2];
#pragma unroll
            for (int np = 0; np < 2; np++) {
                uint32_t r4[4];
                LDSM4(r4, sB + SWZ((n0w + np * 16 + rB) * 128 + ks * 32 + cB));
                b[np * 2][0] = r4[0]; b[np * 2][1] = r4[1];
                b[np * 2 + 1][0] = r4[2]; b[np * 2 + 1][1] = r4[3];
            }
#pragma unroll
            for (int mt = 0; mt < 4; mt++)
                LDSM4(a[mt], sa + SWZ((m0w + mt * 16 + rA) * 128 + ks * 32 + cA));
#pragma unroll
            for (int mt = 0; mt < 4; mt++)
#pragma unroll
                for (int nt = 0; nt < 4; nt++) MMA(acc[mt][nt], a[mt], b[nt]);
        }
    }

    // ---- epilogue: stage fp16 tile in smem (256B rows, SWZ), then coalesce --
    __syncthreads();   // mainloop smem dead; no real cp.async pending
    const int g = lane >> 2, t = lane & 3;
#pragma unroll
    for (int mt = 0; mt < 4; mt++) {
#pragma unroll
        for (int nt = 0; nt < 4; nt++) {
            int row = m0w + mt * 16 + g;
            int colb = (n0w + nt * 8 + t * 2) * 2;
            *(__half2*)(smem + SWZ(row * 256 + colb)) =
                __floats2half2_rn(acc[mt][nt][0], acc[mt][nt][1]);
            *(__half2*)(smem + SWZ((row + 8) * 256 + colb)) =
                __floats2half2_rn(acc[mt][nt][2], acc[mt][nt][3]);
        }
    }
    __syncthreads();
    // copy out: 128 rows x 256B; 16 lanes cover one full row (coalesced 16B each)
#pragma unroll
    for (int k = 0; k < 8; k++) {
        int chunk = tid + k * 256;          // 2048 x 16B chunks
        int row = chunk >> 4, c16 = chunk & 15;
        uint4 v = *(uint4*)(smem + SWZ(row * 256 + c16 * 16));
        *(uint4*)(U + (bm + row) * (size_t)N + bn + c16 * 8) = v;
    }
}

// ---------------- fused prep: x->fp16 remap  +  W0 transpose -----------------
// blocks [0, 6144): conv x (T*B*512 elems, 256/block)
// blocks [6144, 6144+2048): W0 [512,4096] -> wh0 [4096,512] (32x32 tiles)
#define XBLKS ((TLEN * BSZ * 512) / 256)
__global__ __launch_bounds__(256)
void prep_k(const float* __restrict__ x, __half* __restrict__ ah,
            const float* __restrict__ W0, __half* __restrict__ wh0)
{
    if (blockIdx.x < XBLKS) {
        size_t i = (size_t)blockIdx.x * 256 + threadIdx.x;
        int d = i & 511;
        size_t r = i >> 9;
        int b = (int)(r & (BSZ - 1));
        int t = (int)(r >> 11);
        ah[i] = __float2half_rn(x[((size_t)b * TLEN + t) * 512 + d]);
    } else {
        __shared__ float t[32][33];
        int tile = blockIdx.x - XBLKS;       // 2048 tiles: 16 (k) x 128 (n)
        int k0 = (tile >> 7) * 32;
        int n0 = (tile & 127) * 32;
        const int tx = threadIdx.x & 31, ty = threadIdx.x >> 5;  // 32x8
#pragma unroll
        for (int j = 0; j < 32; j += 8)
            t[ty + j][tx] = W0[(size_t)(k0 + ty + j) * 4096 + n0 + tx];
        __syncthreads();
#pragma unroll
        for (int j = 0; j < 32; j += 8)
            wh0[(size_t)(n0 + ty + j) * 512 + k0 + tx] = __float2half_rn(t[tx][ty + j]);
    }
}

// ---------------- SRU recurrence (2-wide, software-pipelined, all-fp16 U) ----
// U row layout: u0 at +0, u1 at +1024, u2 at +2048, resid at +3072 (layer 0).
// w = U row stride (4096 layer 0, 3072 otherwise). resid otherwise from hbuf
// (fp16, in-place overwrite; same thread owns each element).
// g_out!=nullptr (final layer): emit time-sum instead of h.
__global__ __launch_bounds__(256)
void sru_k(const __half* __restrict__ U, int w, int resid_in_u,
           const float* __restrict__ vc, const float* __restrict__ bvec,
           __half* __restrict__ hbuf, float* __restrict__ g_out)
{
    const float SCALE_X = 1.7320508075688772f;
    int idx = blockIdx.x * blockDim.x + threadIdx.x;  // over BSZ*512
    int d = (idx & 511) * 2;
    int b = idx >> 9;
    float2 vf = *(const float2*)(vc + d);
    float2 vr = *(const float2*)(vc + HIDD + d);
    float2 bf = *(const float2*)(bvec + d);
    float2 br = *(const float2*)(bvec + HIDD + d);
    float cx = 0.f, cy = 0.f, gx = 0.f, gy = 0.f;

    // prefetch t=0
    const __half* Up0 = U + (size_t)b * w + d;
    __half2 u0h = *(const __half2*)(Up0);
    __half2 u1h = *(const __half2*)(Up0 + 1024);
    __half2 u2h = *(const __half2*)(Up0 + 2048);
    __half2 xrh;
    if (resid_in_u) xrh = *(const __half2*)(Up0 + 3072);
    else            xrh = *(const __half2*)(hbuf + (size_t)b * HIDD + d);

#pragma unroll
    for (int t = 0; t < TLEN; t++) {
        __half2 u0n = u0h, u1n = u1h, u2n = u2h, xrn = xrh;
        if (t + 1 < TLEN) {
            const __half* Upn = U + ((size_t)(t + 1) * BSZ + b) * w + d;
            u0n = *(const __half2*)(Upn);
            u1n = *(const __half2*)(Upn + 1024);
            u2n = *(const __half2*)(Upn + 2048);
            if (resid_in_u) xrn = *(const __half2*)(Upn + 3072);
            else xrn = *(const __half2*)(hbuf + ((size_t)(t + 1) * BSZ + b) * HIDD + d);
        }
        float2 u0 = __half22float2(u0h);
        float2 u1 = __half22float2(u1h);
        float2 u2 = __half22float2(u2h);
        float2 xr = __half22float2(xrh);
        float fx = sigf(u1.x + vf.x * cx + bf.x);
        float fy = sigf(u1.y + vf.y * cy + bf.y);
        cx = fx * cx + (1.f - fx) * u0.x;
        cy = fy * cy + (1.f - fy) * u0.y;
        float rx = sigf(u2.x + vr.x * cx + br.x);
        float ry = sigf(u2.y + vr.y * cy + br.y);
        float hx = rx * tanhfast(cx) + (1.f - rx) * xr.x * SCALE_X;
        float hy = ry * tanhfast(cy) + (1.f - ry) * xr.y * SCALE_X;
        if (g_out) { gx += hx; gy += hy; }
        else *(__half2*)(hbuf + ((size_t)t * BSZ + b) * HIDD + d) = __floats2half2_rn(hx, hy);
        u0h = u0n; u1h = u1n; u2h = u2n; xrh = xrn;
    }
    if (g_out) *(float2*)(g_out + (size_t)b * HIDD + d) = make_float2(gx, gy);
}

// ---------------- FC head: 8 batch rows per block ----------------------------
__global__ __launch_bounds__(256)
void fc_k(const float* __restrict__ g, const float* __restrict__ w,
          const float* __restrict__ bias, float* __restrict__ out)
{
    __shared__ float gs[8][HIDD];
    const int b0 = blockIdx.x * 8;
    for (int i = threadIdx.x; i < 8 * HIDD; i += 256)
        gs[i >> 10][i & 1023] = g[(size_t)(b0 + (i >> 10)) * HIDD + (i & 1023)];
    __syncthreads();
    const int c = threadIdx.x & 63, bq = threadIdx.x >> 6;   // 4 groups x 2 rows
    if (c < NCLS) {
        float bb = bias[c];
#pragma unroll
        for (int j = 0; j < 2; j++) {
            int bl = bq * 2 + j;
            float s = 0.f;
#pragma unroll 8
            for (int hh = 0; hh < HIDD; hh++) s += gs[bl][hh] * w[hh * NCLS + c];
            out[(size_t)(b0 + bl) * NCLS + c] = s * (1.f / TLEN) + bb;
        }
    }
}

// ---------------- launch -----------------------------------------------------
extern "C" void kernel_launch(void* const* d_in, const int* in_sizes, int n_in,
                              void* d_out, int out_size)
{
    const float* x    = (const float*)d_in[0];
    const float* W0   = (const float*)d_in[1];
    const float* W1   = (const float*)d_in[2];
    const float* W2   = (const float*)d_in[3];
    const float* vc0  = (const float*)d_in[4];
    const float* vc1  = (const float*)d_in[5];
    const float* vc2  = (const float*)d_in[6];
    const float* b0   = (const float*)d_in[7];
    const float* b1   = (const float*)d_in[8];
    const float* b2   = (const float*)d_in[9];
    const float* fcw  = (const float*)d_in[10];
    const float* fcb  = (const float*)d_in[11];
    float* out = (float*)d_out;

    float *gg;
    __half *U, *ah, *wh0, *wh1, *wh2;
    cudaGetSymbolAddress((void**)&U,   g_U);
    cudaGetSymbolAddress((void**)&gg,  g_g);
    cudaGetSymbolAddress((void**)&ah,  g_ah);
    cudaGetSymbolAddress((void**)&wh0, g_wh0);
    cudaGetSymbolAddress((void**)&wh1, g_wh1);
    cudaGetSymbolAddress((void**)&wh2, g_wh2);

    cudaFuncSetAttribute(gemm_tc, cudaFuncAttributeMaxDynamicSharedMemorySize, SMEM_TOTAL);

    const int sruBlocks = (BSZ * 512) / 256;

    // fused prep: x conversion + W0 transpose (one launch)
    prep_k<<<XBLKS + 2048, 256>>>(x, ah, W0, wh0);

    // Layer 0 GEMM (grid.x 32 gemm cols + 16 extra cols = 3072 W1-transpose blocks)
    gemm_tc<<<dim3(32 + 16, MROWS / BM), 256, SMEM_TOTAL>>>(
        ah, wh0, U, 4096, 512, 32, W1, wh1, 1024, 3072);
    sru_k<<<sruBlocks, 256>>>(U, 4096, 1, vc0, b0, ah, nullptr);

    // Layer 1 GEMM (24 gemm cols + 16 extra = W2 transpose)
    gemm_tc<<<dim3(24 + 16, MROWS / BM), 256, SMEM_TOTAL>>>(
        ah, wh1, U, 3072, 1024, 24, W2, wh2, 1024, 3072);
    sru_k<<<sruBlocks, 256>>>(U, 3072, 0, vc1, b1, ah, nullptr);

    // Layer 2 GEMM (no extra blocks); final SRU emits time-sum g
    gemm_tc<<<dim3(24, MROWS / BM), 256, SMEM_TOTAL>>>(
        ah, wh2, U, 3072, 1024, 24, nullptr, nullptr, 0, 0);
    sru_k<<<sruBlocks, 256>>>(U, 3072, 0, vc2, b2, ah, gg);

    // Head
    fc_k<<<BSZ / 8, 256>>>(gg, fcw, fcb, out);
}